// round 9
// baseline (speedup 1.0000x reference)
#include <cuda_runtime.h>
#include <cstdint>

#define BB   256
#define CTXD 512
#define DOF  6
#define WSZ  300
#define JZ   306          // DOF + WSZ
#define JZP  308          // padded to float4 multiple
#define PG   256
#define PW   512
#define HG   256
#define HW   512
#define NL   2
#define MS   20
#define STEPS 19
#define GOFF (BB*MS*DOF)  // offset of ws in out (30720)

typedef unsigned long long u64;

// ---------------- scratch (device globals: no allocs allowed) ----------------
__device__ float d_Mg[(size_t)BB*PG*DOF];            // 1.5 MB
__device__ float d_Mw[(size_t)BB*PW*JZP];            // ~161 MB (fp32 for accuracy)
__device__ float d_xpre[BB*PG];
__device__ float d_ypre[BB*PW];
__device__ float d_xg[BB*PG];
__device__ float d_yw[BB*PW];
__device__ float d_gh[NL*BB*HG];
__device__ float d_gc[NL*BB*HG];
__device__ float d_wh[NL*BB*HW];
__device__ float d_wc[NL*BB*HW];
__device__ float d_gates_g[BB*4*HG];
__device__ float d_gates_w[BB*4*HW];
__device__ float d_bias_g[NL*4*HG];
__device__ float d_bias_w[NL*4*HW];

__device__ __forceinline__ float sigmoidf_(float x) { return 1.0f / (1.0f + expf(-x)); }

__device__ __forceinline__ float2 unpk_(u64 v) {
    float2 r; asm("mov.b64 {%0, %1}, %2;" : "=f"(r.x), "=f"(r.y) : "l"(v)); return r;
}
__device__ __forceinline__ u64 fma2_(u64 a, u64 b, u64 c) {
    u64 d; asm("fma.rn.f32x2 %0, %1, %2, %3;" : "=l"(d) : "l"(a), "l"(b), "l"(c)); return d;
}

// ---------------- init ---------------------------------------------------------
__global__ void init_kernel(const float* __restrict__ g0, const float* __restrict__ w0,
                            const float* __restrict__ lg_bih, const float* __restrict__ lg_bhh,
                            const float* __restrict__ lw_bih, const float* __restrict__ lw_bhh,
                            float* __restrict__ out)
{
    int tid = blockIdx.x * blockDim.x + threadIdx.x;
    int nt  = gridDim.x * blockDim.x;
    for (int i = tid; i < NL*BB*HG; i += nt) { d_gh[i] = 0.f; d_gc[i] = 0.f; }
    for (int i = tid; i < NL*BB*HW; i += nt) { d_wh[i] = 0.f; d_wc[i] = 0.f; }
    for (int i = tid; i < NL*4*HG; i += nt) d_bias_g[i] = lg_bih[i] + lg_bhh[i];
    for (int i = tid; i < NL*4*HW; i += nt) d_bias_w[i] = lw_bih[i] + lw_bhh[i];
    for (int i = tid; i < BB*PW; i += nt) {   // zero Mw padding columns
        d_Mw[(size_t)i*JZP + 306] = 0.f;
        d_Mw[(size_t)i*JZP + 307] = 0.f;
    }
    for (int i = tid; i < BB*DOF; i += nt) {
        int b = i / DOF, j = i % DOF;
        out[b*(MS*DOF) + j] = g0[i];
    }
    for (int i = tid; i < BB*WSZ; i += nt) {
        int b = i / WSZ, j = i % WSZ;
        out[GOFF + b*(MS*WSZ) + j] = w0[i];
    }
}

// ---------------- precompute M_g (fp32) ---------------------------------------
__global__ void pre_Mg_kernel(const float* __restrict__ ctx, const float* __restrict__ bgW)
{
    int o = blockIdx.x;
    __shared__ float w[CTXD*DOF];
    for (int i = threadIdx.x; i < CTXD*DOF; i += blockDim.x)
        w[i] = bgW[(size_t)o*CTXD*DOF + i];
    __syncthreads();
    int b = threadIdx.x;
    const float* cr = ctx + (size_t)b*CTXD;
    float acc[DOF];
    #pragma unroll
    for (int j = 0; j < DOF; j++) acc[j] = 0.f;
    for (int i = 0; i < CTXD; i++) {
        float c = cr[i];
        #pragma unroll
        for (int j = 0; j < DOF; j++) acc[j] += c * w[i*DOF + j];
    }
    #pragma unroll
    for (int j = 0; j < DOF; j++)
        d_Mg[((size_t)b*PG + o)*DOF + j] = acc[j];
}

// ---------------- dual-descriptor fp32x2 GEMM, 128x64 tile --------------------
// C = A(MxK)*B (+ A2(MxK2)*B2) (+bias) (tanh?).  transB=1: B is NxK (NT).
// transB=0: B is KxN (NN).
struct GDesc {
    const float *A, *B, *A2, *B2, *bias;
    float *C;
    int lda, ldb, lda2, ldb2, ldc;
    int M, N, K, K2;
    int transB, act, gx;
    long long strideB, strideC;
};

__global__ void __launch_bounds__(256)
gemm2_kernel(GDesc d0, GDesc d1, int z0)
{
    const int z = blockIdx.z;
    GDesc d = (z < z0) ? d0 : d1;
    const int bat = (z < z0) ? z : 0;
    if ((int)blockIdx.x >= d.gx || d.M == 0) return;

    const float* Bb0 = d.B + (long long)bat * d.strideB;
    float* C = d.C + (long long)bat * d.strideC;

    const int bm = blockIdx.y * 128;
    const int bn = blockIdx.x * 64;

    __shared__ __align__(16) float sA[2][16][132];   // [k][m]
    __shared__ __align__(16) float sBd[2][16][136];  // [k][2n] duplicated

    const int tid = threadIdx.x;
    const int tx = tid & 15;            // n group (4 cols)
    const int ty = tid >> 4;            // m group (8 rows)
    const int ra = tid >> 1;            // A row 0..127
    const int ca = (tid & 1) << 3;      // A k offset 0/8
    const int rb = tid >> 2;            // B-NT n row 0..63
    const int cb = (tid & 3) << 2;      // B-NT k offset
    const int nkk = tid >> 4;           // B-NN k row 0..15
    const int nn4 = (tid & 15) << 2;    // B-NN n offset

    u64 acc[4][4];
    #pragma unroll
    for (int p = 0; p < 4; p++)
        #pragma unroll
        for (int j = 0; j < 4; j++) acc[p][j] = 0ull;

    #pragma unroll 1
    for (int pass = 0; pass < 2; ++pass) {
        const float* Ap = pass ? d.A2 : d.A;
        const float* Bp = pass ? d.B2 : Bb0;
        const int lA = pass ? d.lda2 : d.lda;
        const int lB = pass ? d.ldb2 : d.ldb;
        const int Kp = pass ? d.K2 : d.K;
        if (Ap == nullptr || Kp <= 0) continue;
        const int nc = Kp >> 4;

        // ---- load chunk 0 ----
        float4 pa0 = *(const float4*)(Ap + (size_t)(bm + ra)*lA + ca);
        float4 pa1 = *(const float4*)(Ap + (size_t)(bm + ra)*lA + ca + 4);
        float4 pb;
        if (d.transB) {
            int n = bn + rb;
            pb = (n < d.N) ? *(const float4*)(Bp + (size_t)n*lB + cb)
                           : make_float4(0.f, 0.f, 0.f, 0.f);
        } else {
            const float* src = Bp + (size_t)nkk*lB + bn + nn4;
            pb.x = (bn + nn4 + 0 < d.N) ? src[0] : 0.f;
            pb.y = (bn + nn4 + 1 < d.N) ? src[1] : 0.f;
            pb.z = (bn + nn4 + 2 < d.N) ? src[2] : 0.f;
            pb.w = (bn + nn4 + 3 < d.N) ? src[3] : 0.f;
        }
        {
            sA[0][ca+0][ra] = pa0.x; sA[0][ca+1][ra] = pa0.y;
            sA[0][ca+2][ra] = pa0.z; sA[0][ca+3][ra] = pa0.w;
            sA[0][ca+4][ra] = pa1.x; sA[0][ca+5][ra] = pa1.y;
            sA[0][ca+6][ra] = pa1.z; sA[0][ca+7][ra] = pa1.w;
            if (d.transB) {
                sBd[0][cb+0][2*rb] = pb.x; sBd[0][cb+0][2*rb+1] = pb.x;
                sBd[0][cb+1][2*rb] = pb.y; sBd[0][cb+1][2*rb+1] = pb.y;
                sBd[0][cb+2][2*rb] = pb.z; sBd[0][cb+2][2*rb+1] = pb.z;
                sBd[0][cb+3][2*rb] = pb.w; sBd[0][cb+3][2*rb+1] = pb.w;
            } else {
                sBd[0][nkk][2*(nn4+0)] = pb.x; sBd[0][nkk][2*(nn4+0)+1] = pb.x;
                sBd[0][nkk][2*(nn4+1)] = pb.y; sBd[0][nkk][2*(nn4+1)+1] = pb.y;
                sBd[0][nkk][2*(nn4+2)] = pb.z; sBd[0][nkk][2*(nn4+2)+1] = pb.z;
                sBd[0][nkk][2*(nn4+3)] = pb.w; sBd[0][nkk][2*(nn4+3)+1] = pb.w;
            }
        }
        __syncthreads();

        int buf = 0;
        #pragma unroll 1
        for (int c = 0; c < nc; ++c) {
            const bool more = (c + 1 < nc);
            float4 na0, na1, nb;
            if (more) {
                const int k0 = (c + 1) << 4;
                na0 = *(const float4*)(Ap + (size_t)(bm + ra)*lA + k0 + ca);
                na1 = *(const float4*)(Ap + (size_t)(bm + ra)*lA + k0 + ca + 4);
                if (d.transB) {
                    int n = bn + rb;
                    nb = (n < d.N) ? *(const float4*)(Bp + (size_t)n*lB + k0 + cb)
                                   : make_float4(0.f, 0.f, 0.f, 0.f);
                } else {
                    const float* src = Bp + (size_t)(k0 + nkk)*lB + bn + nn4;
                    nb.x = (bn + nn4 + 0 < d.N) ? src[0] : 0.f;
                    nb.y = (bn + nn4 + 1 < d.N) ? src[1] : 0.f;
                    nb.z = (bn + nn4 + 2 < d.N) ? src[2] : 0.f;
                    nb.w = (bn + nn4 + 3 < d.N) ? src[3] : 0.f;
                }
            }
            // ---- compute on buf: pure LDS.64 + FMA2 inner loop ----
            #pragma unroll
            for (int kk = 0; kk < 16; kk++) {
                const u64 a0 = *(const u64*)&sA[buf][kk][ty*8 + 0];
                const u64 a1 = *(const u64*)&sA[buf][kk][ty*8 + 2];
                const u64 a2 = *(const u64*)&sA[buf][kk][ty*8 + 4];
                const u64 a3 = *(const u64*)&sA[buf][kk][ty*8 + 6];
                #pragma unroll
                for (int n = 0; n < 4; n++) {
                    const u64 b = *(const u64*)&sBd[buf][kk][2*(tx*4 + n)];
                    acc[0][n] = fma2_(a0, b, acc[0][n]);
                    acc[1][n] = fma2_(a1, b, acc[1][n]);
                    acc[2][n] = fma2_(a2, b, acc[2][n]);
                    acc[3][n] = fma2_(a3, b, acc[3][n]);
                }
            }
            if (more) {
                const int nbuf = buf ^ 1;
                sA[nbuf][ca+0][ra] = na0.x; sA[nbuf][ca+1][ra] = na0.y;
                sA[nbuf][ca+2][ra] = na0.z; sA[nbuf][ca+3][ra] = na0.w;
                sA[nbuf][ca+4][ra] = na1.x; sA[nbuf][ca+5][ra] = na1.y;
                sA[nbuf][ca+6][ra] = na1.z; sA[nbuf][ca+7][ra] = na1.w;
                if (d.transB) {
                    sBd[nbuf][cb+0][2*rb] = nb.x; sBd[nbuf][cb+0][2*rb+1] = nb.x;
                    sBd[nbuf][cb+1][2*rb] = nb.y; sBd[nbuf][cb+1][2*rb+1] = nb.y;
                    sBd[nbuf][cb+2][2*rb] = nb.z; sBd[nbuf][cb+2][2*rb+1] = nb.z;
                    sBd[nbuf][cb+3][2*rb] = nb.w; sBd[nbuf][cb+3][2*rb+1] = nb.w;
                } else {
                    sBd[nbuf][nkk][2*(nn4+0)] = nb.x; sBd[nbuf][nkk][2*(nn4+0)+1] = nb.x;
                    sBd[nbuf][nkk][2*(nn4+1)] = nb.y; sBd[nbuf][nkk][2*(nn4+1)+1] = nb.y;
                    sBd[nbuf][nkk][2*(nn4+2)] = nb.z; sBd[nbuf][nkk][2*(nn4+2)+1] = nb.z;
                    sBd[nbuf][nkk][2*(nn4+3)] = nb.w; sBd[nbuf][nkk][2*(nn4+3)+1] = nb.w;
                }
            }
            __syncthreads();
            buf ^= 1;
        }
    }

    // ---- epilogue ----
    const int n0 = bn + tx*4;
    const int m0 = bm + ty*8;
    float bb[4] = {0.f, 0.f, 0.f, 0.f};
    if (d.bias) {
        #pragma unroll
        for (int j = 0; j < 4; j++) if (n0 + j < d.N) bb[j] = d.bias[n0 + j];
    }
    const bool vec = ((d.ldc & 3) == 0) && ((((size_t)C) & 15) == 0) && (bn + 64 <= d.N);
    #pragma unroll
    for (int p = 0; p < 4; p++) {
        const float2 v0 = unpk_(acc[p][0]);
        const float2 v1 = unpk_(acc[p][1]);
        const float2 v2 = unpk_(acc[p][2]);
        const float2 v3 = unpk_(acc[p][3]);
        float4 r0 = make_float4(v0.x + bb[0], v1.x + bb[1], v2.x + bb[2], v3.x + bb[3]);
        float4 r1 = make_float4(v0.y + bb[0], v1.y + bb[1], v2.y + bb[2], v3.y + bb[3]);
        if (d.act) {
            r0.x = tanhf(r0.x); r0.y = tanhf(r0.y); r0.z = tanhf(r0.z); r0.w = tanhf(r0.w);
            r1.x = tanhf(r1.x); r1.y = tanhf(r1.y); r1.z = tanhf(r1.z); r1.w = tanhf(r1.w);
        }
        const int m = m0 + 2*p;
        if (vec) {
            *(float4*)(C + (size_t)m*d.ldc + n0)     = r0;
            *(float4*)(C + (size_t)(m+1)*d.ldc + n0) = r1;
        } else {
            const float rr0[4] = {r0.x, r0.y, r0.z, r0.w};
            const float rr1[4] = {r1.x, r1.y, r1.z, r1.w};
            #pragma unroll
            for (int j = 0; j < 4; j++) {
                if (n0 + j < d.N) {
                    C[(size_t)m*d.ldc + n0 + j]     = rr0[j];
                    C[(size_t)(m+1)*d.ldc + n0 + j] = rr1[j];
                }
            }
        }
    }
}

// ---------------- per-step bilinear matvecs (fp32, 4 rows/warp, float4) ------
__global__ void bilinear_kernel(int t, const float* __restrict__ bg_b,
                                const float* __restrict__ bw_b,
                                const float* __restrict__ out)
{
    const int b = blockIdx.x;
    __shared__ __align__(16) float zs[JZP];
    const int tid = threadIdx.x;
    for (int i = tid; i < JZP; i += blockDim.x) {
        float v = 0.f;
        if (i < DOF)            v = out[(size_t)b*MS*DOF + t*DOF + i];
        else if (i - DOF < WSZ) v = out[GOFF + (size_t)b*MS*WSZ + t*WSZ + (i - DOF)];
        zs[i] = v;
    }
    __syncthreads();
    if (blockIdx.y < PW/32) {
        const int w = tid >> 5;
        const int lane = tid & 31;
        const int o0 = blockIdx.y * 32 + w * 4;
        const float4* m0 = (const float4*)(d_Mw + ((size_t)b*PW + o0 + 0)*JZP);
        const float4* m1 = (const float4*)(d_Mw + ((size_t)b*PW + o0 + 1)*JZP);
        const float4* m2 = (const float4*)(d_Mw + ((size_t)b*PW + o0 + 2)*JZP);
        const float4* m3 = (const float4*)(d_Mw + ((size_t)b*PW + o0 + 3)*JZP);
        const float4* z4 = (const float4*)zs;
        float s0 = 0.f, s1 = 0.f, s2 = 0.f, s3 = 0.f;
        #pragma unroll 1
        for (int j4 = lane; j4 < JZP/4; j4 += 32) {
            const float4 zv = z4[j4];
            const float4 v0 = m0[j4];
            const float4 v1 = m1[j4];
            const float4 v2 = m2[j4];
            const float4 v3 = m3[j4];
            s0 += v0.x*zv.x + v0.y*zv.y + v0.z*zv.z + v0.w*zv.w;
            s1 += v1.x*zv.x + v1.y*zv.y + v1.z*zv.z + v1.w*zv.w;
            s2 += v2.x*zv.x + v2.y*zv.y + v2.z*zv.z + v2.w*zv.w;
            s3 += v3.x*zv.x + v3.y*zv.y + v3.z*zv.z + v3.w*zv.w;
        }
        #pragma unroll
        for (int off = 16; off; off >>= 1) {
            s0 += __shfl_down_sync(0xffffffffu, s0, off);
            s1 += __shfl_down_sync(0xffffffffu, s1, off);
            s2 += __shfl_down_sync(0xffffffffu, s2, off);
            s3 += __shfl_down_sync(0xffffffffu, s3, off);
        }
        if (lane == 0) {
            d_ypre[b*PW + o0 + 0] = s0 + bw_b[o0 + 0];
            d_ypre[b*PW + o0 + 1] = s1 + bw_b[o0 + 1];
            d_ypre[b*PW + o0 + 2] = s2 + bw_b[o0 + 2];
            d_ypre[b*PW + o0 + 3] = s3 + bw_b[o0 + 3];
        }
    } else {
        // x branch: tid is o (256 outputs, 6-elem dot), fp32 Mg
        const float* mg = d_Mg + ((size_t)b*PG + tid)*DOF;
        float s = bg_b[tid];
        #pragma unroll
        for (int j = 0; j < DOF; j++) s += mg[j] * zs[j];
        d_xpre[b*PG + tid] = s;
    }
}

// ---------------- merged LSTM pointwise (g-chain + w-chain) ------------------
__global__ void lstm_point2_kernel(const float* __restrict__ gg, const float* __restrict__ gw,
                                   float* __restrict__ hgp, float* __restrict__ cgp,
                                   float* __restrict__ hwp, float* __restrict__ cwp)
{
    int idx = blockIdx.x * blockDim.x + threadIdx.x;
    const float* gates; float* h; float* c; int H;
    if (idx < BB*HG) { gates = gg; h = hgp; c = cgp; H = HG; }
    else {
        idx -= BB*HG;
        if (idx >= BB*HW) return;
        gates = gw; h = hwp; c = cwp; H = HW;
    }
    const int b = idx / H, j = idx % H;
    const float* g = gates + (size_t)b*4*H;
    const float ig = sigmoidf_(g[j]);
    const float fg = sigmoidf_(g[H + j]);
    const float gv = tanhf(g[2*H + j]);
    const float og = sigmoidf_(g[3*H + j]);
    const float cn = fg * c[idx] + ig * gv;
    c[idx] = cn;
    h[idx] = og * tanhf(cn);
}

// ---------------- host helpers -----------------------------------------------
static inline GDesc mk(const float* A, int lda, const float* B, int ldb, int transB,
                       const float* A2, int lda2, const float* B2, int ldb2,
                       const float* bias, float* C, int ldc,
                       int M, int N, int K, int K2, int act,
                       long long sB = 0, long long sC = 0)
{
    GDesc d;
    d.A = A; d.B = B; d.A2 = A2; d.B2 = B2; d.bias = bias; d.C = C;
    d.lda = lda; d.ldb = ldb; d.lda2 = lda2; d.ldb2 = ldb2; d.ldc = ldc;
    d.M = M; d.N = N; d.K = K; d.K2 = K2;
    d.transB = transB; d.act = act; d.gx = (N + 63) / 64;
    d.strideB = sB; d.strideC = sC;
    return d;
}

extern "C" void kernel_launch(void* const* d_in, const int* in_sizes, int n_in,
                              void* d_out, int out_size)
{
    const float* ctx    = (const float*)d_in[0];
    const float* goal0  = (const float*)d_in[1];
    const float* w0     = (const float*)d_in[2];
    const float* bg_W   = (const float*)d_in[3];
    const float* bg_b   = (const float*)d_in[4];
    const float* bw_W   = (const float*)d_in[5];
    const float* bw_b   = (const float*)d_in[6];
    const float* fcg_W  = (const float*)d_in[7];
    const float* fcg_b  = (const float*)d_in[8];
    const float* fcw_W  = (const float*)d_in[9];
    const float* fcw_b  = (const float*)d_in[10];
    const float* lg_Wih = (const float*)d_in[11];
    const float* lg_Whh = (const float*)d_in[12];
    const float* lg_bih = (const float*)d_in[13];
    const float* lg_bhh = (const float*)d_in[14];
    const float* lw_Wih = (const float*)d_in[15];
    const float* lw_Whh = (const float*)d_in[16];
    const float* lw_bih = (const float*)d_in[17];
    const float* lw_bhh = (const float*)d_in[18];
    const float* og_W   = (const float*)d_in[19];
    const float* og_b   = (const float*)d_in[20];
    const float* ow_W   = (const float*)d_in[21];
    const float* ow_b   = (const float*)d_in[22];
    float* out = (float*)d_out;

    float *Mw, *xpre, *ypre, *xg, *yw, *gh, *gc, *wh, *wc, *ggb, *gwb, *bias_g, *bias_w;
    cudaGetSymbolAddress((void**)&Mw, d_Mw);
    cudaGetSymbolAddress((void**)&xpre, d_xpre);
    cudaGetSymbolAddress((void**)&ypre, d_ypre);
    cudaGetSymbolAddress((void**)&xg, d_xg);
    cudaGetSymbolAddress((void**)&yw, d_yw);
    cudaGetSymbolAddress((void**)&gh, d_gh);
    cudaGetSymbolAddress((void**)&gc, d_gc);
    cudaGetSymbolAddress((void**)&wh, d_wh);
    cudaGetSymbolAddress((void**)&wc, d_wc);
    cudaGetSymbolAddress((void**)&ggb, d_gates_g);
    cudaGetSymbolAddress((void**)&gwb, d_gates_w);
    cudaGetSymbolAddress((void**)&bias_g, d_bias_g);
    cudaGetSymbolAddress((void**)&bias_w, d_bias_w);

    GDesc empty = {};
    empty.M = 0; empty.gx = 0;

    // --- init + precompute (context is step-invariant) ---
    init_kernel<<<256, 256>>>(goal0, w0, lg_bih, lg_bhh, lw_bih, lw_bhh, out);
    pre_Mg_kernel<<<PG, 256>>>(ctx, bg_W);

    // M_w[b,o,j] = sum_i ctx[b,i] * bw_W[o,i,j] : batched over o (z = o)
    {
        GDesc dmw = mk(ctx, CTXD, bw_W, JZ, /*transB=*/0,
                       nullptr, 0, nullptr, 0, nullptr,
                       Mw, PW*JZP, BB, JZ, CTXD, 0, 0,
                       (long long)CTXD*JZ, (long long)JZP);
        gemm2_kernel<<<dim3(dmw.gx, BB/128, PW), 256>>>(dmw, empty, PW);
    }

    for (int t = 0; t < STEPS; ++t) {
        // 1. bilinear matvecs
        bilinear_kernel<<<dim3(BB, PW/32 + 1), 256>>>(t, bg_b, bw_b, out);

        // 2. fc + tanh (both branches, one launch)
        {
            GDesc dg = mk(xpre, PG, fcg_W, PG, 1, nullptr, 0, nullptr, 0,
                          fcg_b, xg, PG, BB, PG, PG, 0, 1);
            GDesc dw = mk(ypre, PW, fcw_W, PW, 1, nullptr, 0, nullptr, 0,
                          fcw_b, yw, PW, BB, PW, PW, 0, 1);
            int gx = dg.gx > dw.gx ? dg.gx : dw.gx;
            gemm2_kernel<<<dim3(gx, BB/128, 2), 256>>>(dg, dw, 1);
        }

        // 3+4. LSTM layers (g-chain and w-chain gate GEMMs merged per layer)
        for (int l = 0; l < NL; ++l) {
            const float* ing = (l == 0) ? xg : gh;
            const float* inw = (l == 0) ? yw : wh;
            GDesc dg = mk(ing, (l == 0) ? PG : HG,
                          lg_Wih + (size_t)l*4*HG*PG, (l == 0) ? PG : HG, 1,
                          gh + (size_t)l*BB*HG, HG,
                          lg_Whh + (size_t)l*4*HG*HG, HG,
                          bias_g + l*4*HG, ggb, 4*HG,
                          BB, 4*HG, (l == 0) ? PG : HG, HG, 0);
            GDesc dw = mk(inw, (l == 0) ? PW : HW,
                          lw_Wih + (size_t)l*4*HW*PW, (l == 0) ? PW : HW, 1,
                          wh + (size_t)l*BB*HW, HW,
                          lw_Whh + (size_t)l*4*HW*HW, HW,
                          bias_w + l*4*HW, gwb, 4*HW,
                          BB, 4*HW, (l == 0) ? PW : HW, HW, 0);
            int gx = dg.gx > dw.gx ? dg.gx : dw.gx;
            gemm2_kernel<<<dim3(gx, BB/128, 2), 256>>>(dg, dw, 1);
            lstm_point2_kernel<<<(BB*HG + BB*HW + 255)/256, 256>>>(
                ggb, gwb,
                gh + (size_t)l*BB*HG, gc + (size_t)l*BB*HG,
                wh + (size_t)l*BB*HW, wc + (size_t)l*BB*HW);
        }

        // 5. output projections (merged), written into out rows t+1
        {
            GDesc dg = mk(gh + (size_t)1*BB*HG, HG, og_W, HG, 1, nullptr, 0, nullptr, 0,
                          og_b, out + (t + 1)*DOF, MS*DOF, BB, DOF, HG, 0, 0);
            GDesc dw = mk(wh + (size_t)1*BB*HW, HW, ow_W, HW, 1, nullptr, 0, nullptr, 0,
                          ow_b, out + GOFF + (t + 1)*WSZ, MS*WSZ, BB, WSZ, HW, 0, 0);
            int gx = dg.gx > dw.gx ? dg.gx : dw.gx;
            gemm2_kernel<<<dim3(gx, BB/128, 2), 256>>>(dg, dw, 1);
        }
    }
}

// round 10
// speedup vs baseline: 1.3795x; 1.3795x over previous
#include <cuda_runtime.h>
#include <cstdint>

#define BB   256
#define CTXD 512
#define DOF  6
#define WSZ  300
#define JZ   306          // DOF + WSZ
#define JZP  308          // padded to float4 multiple
#define PG   256
#define PW   512
#define HG   256
#define HW   512
#define NL   2
#define MS   20
#define STEPS 19
#define GOFF (BB*MS*DOF)  // offset of ws in out (30720)

#define BROW 134          // B smem row words (swizzled dup layout, even => LDS.64 aligned)

typedef unsigned long long u64;

// ---------------- scratch (device globals: no allocs allowed) ----------------
__device__ float d_Mg[(size_t)BB*PG*DOF];            // 1.5 MB
__device__ float d_Mw[(size_t)BB*PW*JZP];            // ~161 MB (fp32 for accuracy)
__device__ float d_xpre[BB*PG];
__device__ float d_ypre[BB*PW];
__device__ float d_xg[BB*PG];
__device__ float d_yw[BB*PW];
__device__ float d_gh[NL*BB*HG];
__device__ float d_gc[NL*BB*HG];
__device__ float d_wh[NL*BB*HW];
__device__ float d_wc[NL*BB*HW];
__device__ float d_gates_g[BB*4*HG];
__device__ float d_gates_w[BB*4*HW];
__device__ float d_bias_g[NL*4*HG];
__device__ float d_bias_w[NL*4*HW];

__device__ __forceinline__ float sigmoidf_(float x) { return 1.0f / (1.0f + expf(-x)); }

__device__ __forceinline__ float2 unpk_(u64 v) {
    float2 r; asm("mov.b64 {%0, %1}, %2;" : "=f"(r.x), "=f"(r.y) : "l"(v)); return r;
}
__device__ __forceinline__ u64 fma2_(u64 a, u64 b, u64 c) {
    u64 d; asm("fma.rn.f32x2 %0, %1, %2, %3;" : "=l"(d) : "l"(a), "l"(b), "l"(c)); return d;
}
// word offset of duplicated pair for column n within a B smem row
__device__ __forceinline__ int bwoff_(int n) { return 2*((n >> 2) + (n & 3)*17); }

// ---------------- init ---------------------------------------------------------
__global__ void init_kernel(const float* __restrict__ g0, const float* __restrict__ w0,
                            const float* __restrict__ lg_bih, const float* __restrict__ lg_bhh,
                            const float* __restrict__ lw_bih, const float* __restrict__ lw_bhh,
                            float* __restrict__ out)
{
    int tid = blockIdx.x * blockDim.x + threadIdx.x;
    int nt  = gridDim.x * blockDim.x;
    for (int i = tid; i < NL*BB*HG; i += nt) { d_gh[i] = 0.f; d_gc[i] = 0.f; }
    for (int i = tid; i < NL*BB*HW; i += nt) { d_wh[i] = 0.f; d_wc[i] = 0.f; }
    for (int i = tid; i < NL*4*HG; i += nt) d_bias_g[i] = lg_bih[i] + lg_bhh[i];
    for (int i = tid; i < NL*4*HW; i += nt) d_bias_w[i] = lw_bih[i] + lw_bhh[i];
    for (int i = tid; i < BB*PW; i += nt) {   // zero Mw padding columns
        d_Mw[(size_t)i*JZP + 306] = 0.f;
        d_Mw[(size_t)i*JZP + 307] = 0.f;
    }
    for (int i = tid; i < BB*DOF; i += nt) {
        int b = i / DOF, j = i % DOF;
        out[b*(MS*DOF) + j] = g0[i];
    }
    for (int i = tid; i < BB*WSZ; i += nt) {
        int b = i / WSZ, j = i % WSZ;
        out[GOFF + b*(MS*WSZ) + j] = w0[i];
    }
}

// ---------------- precompute M_g (fp32) ---------------------------------------
__global__ void pre_Mg_kernel(const float* __restrict__ ctx, const float* __restrict__ bgW)
{
    int o = blockIdx.x;
    __shared__ float w[CTXD*DOF];
    for (int i = threadIdx.x; i < CTXD*DOF; i += blockDim.x)
        w[i] = bgW[(size_t)o*CTXD*DOF + i];
    __syncthreads();
    int b = threadIdx.x;
    const float* cr = ctx + (size_t)b*CTXD;
    float acc[DOF];
    #pragma unroll
    for (int j = 0; j < DOF; j++) acc[j] = 0.f;
    for (int i = 0; i < CTXD; i++) {
        float c = cr[i];
        #pragma unroll
        for (int j = 0; j < DOF; j++) acc[j] += c * w[i*DOF + j];
    }
    #pragma unroll
    for (int j = 0; j < DOF; j++)
        d_Mg[((size_t)b*PG + o)*DOF + j] = acc[j];
}

// ---------------- dual-descriptor fp32x2 GEMM, 128x64 tile --------------------
// C = A(MxK)*B (+ A2(MxK2)*B2) (+bias) (tanh?).  transB=1: B is NxK (NT).
// transB=0: B is KxN (NN).
struct GDesc {
    const float *A, *B, *A2, *B2, *bias;
    float *C;
    int lda, ldb, lda2, ldb2, ldc;
    int M, N, K, K2;
    int transB, act, gx;
    long long strideB, strideC;
};

__global__ void __launch_bounds__(256)
gemm2_kernel(GDesc d0, GDesc d1, int z0)
{
    const int z = blockIdx.z;
    GDesc d = (z < z0) ? d0 : d1;
    const int bat = (z < z0) ? z : 0;
    if ((int)blockIdx.x >= d.gx || d.M == 0) return;

    const float* Bb0 = d.B + (long long)bat * d.strideB;
    float* C = d.C + (long long)bat * d.strideC;

    const int bm = blockIdx.y * 128;
    const int bn = blockIdx.x * 64;

    __shared__ __align__(16) float sA[2][16][132];   // [k][m]
    __shared__ __align__(16) float sBw[2][16][BROW]; // [k][swizzled dup n-pairs]

    const int tid = threadIdx.x;
    const int tx = tid & 15;            // n group (4 cols)
    const int ty = tid >> 4;            // m group (8 rows)
    const int ra = tid >> 1;            // A row 0..127
    const int ca = (tid & 1) << 3;      // A k offset 0/8
    const int rb = tid >> 2;            // B-NT n row 0..63
    const int cb = (tid & 3) << 2;      // B-NT k offset
    const int nkk = tid >> 4;           // B-NN k row 0..15
    const int nn4 = (tid & 15) << 2;    // B-NN n offset
    const int wo_nt = bwoff_(rb);       // dup-pair word offset for NT stores
    const int wb = 2*tx;                // base read word for inner loop

    u64 acc[4][4];
    #pragma unroll
    for (int p = 0; p < 4; p++)
        #pragma unroll
        for (int j = 0; j < 4; j++) acc[p][j] = 0ull;

    #pragma unroll 1
    for (int pass = 0; pass < 2; ++pass) {
        const float* Ap = pass ? d.A2 : d.A;
        const float* Bp = pass ? d.B2 : Bb0;
        const int lA = pass ? d.lda2 : d.lda;
        const int lB = pass ? d.ldb2 : d.ldb;
        const int Kp = pass ? d.K2 : d.K;
        if (Ap == nullptr || Kp <= 0) continue;
        const int nc = Kp >> 4;

        // ---- load chunk 0 ----
        float4 pa0 = *(const float4*)(Ap + (size_t)(bm + ra)*lA + ca);
        float4 pa1 = *(const float4*)(Ap + (size_t)(bm + ra)*lA + ca + 4);
        float4 pb;
        if (d.transB) {
            int n = bn + rb;
            pb = (n < d.N) ? *(const float4*)(Bp + (size_t)n*lB + cb)
                           : make_float4(0.f, 0.f, 0.f, 0.f);
        } else {
            const float* src = Bp + (size_t)nkk*lB + bn + nn4;
            pb.x = (bn + nn4 + 0 < d.N) ? src[0] : 0.f;
            pb.y = (bn + nn4 + 1 < d.N) ? src[1] : 0.f;
            pb.z = (bn + nn4 + 2 < d.N) ? src[2] : 0.f;
            pb.w = (bn + nn4 + 3 < d.N) ? src[3] : 0.f;
        }
        {
            sA[0][ca+0][ra] = pa0.x; sA[0][ca+1][ra] = pa0.y;
            sA[0][ca+2][ra] = pa0.z; sA[0][ca+3][ra] = pa0.w;
            sA[0][ca+4][ra] = pa1.x; sA[0][ca+5][ra] = pa1.y;
            sA[0][ca+6][ra] = pa1.z; sA[0][ca+7][ra] = pa1.w;
            if (d.transB) {
                *(float2*)&sBw[0][cb+0][wo_nt] = make_float2(pb.x, pb.x);
                *(float2*)&sBw[0][cb+1][wo_nt] = make_float2(pb.y, pb.y);
                *(float2*)&sBw[0][cb+2][wo_nt] = make_float2(pb.z, pb.z);
                *(float2*)&sBw[0][cb+3][wo_nt] = make_float2(pb.w, pb.w);
            } else {
                *(float2*)&sBw[0][nkk][bwoff_(nn4+0)] = make_float2(pb.x, pb.x);
                *(float2*)&sBw[0][nkk][bwoff_(nn4+1)] = make_float2(pb.y, pb.y);
                *(float2*)&sBw[0][nkk][bwoff_(nn4+2)] = make_float2(pb.z, pb.z);
                *(float2*)&sBw[0][nkk][bwoff_(nn4+3)] = make_float2(pb.w, pb.w);
            }
        }
        __syncthreads();

        int buf = 0;
        #pragma unroll 1
        for (int c = 0; c < nc; ++c) {
            const bool more = (c + 1 < nc);
            float4 na0, na1, nb;
            if (more) {
                const int k0 = (c + 1) << 4;
                na0 = *(const float4*)(Ap + (size_t)(bm + ra)*lA + k0 + ca);
                na1 = *(const float4*)(Ap + (size_t)(bm + ra)*lA + k0 + ca + 4);
                if (d.transB) {
                    int n = bn + rb;
                    nb = (n < d.N) ? *(const float4*)(Bp + (size_t)n*lB + k0 + cb)
                                   : make_float4(0.f, 0.f, 0.f, 0.f);
                } else {
                    const float* src = Bp + (size_t)(k0 + nkk)*lB + bn + nn4;
                    nb.x = (bn + nn4 + 0 < d.N) ? src[0] : 0.f;
                    nb.y = (bn + nn4 + 1 < d.N) ? src[1] : 0.f;
                    nb.z = (bn + nn4 + 2 < d.N) ? src[2] : 0.f;
                    nb.w = (bn + nn4 + 3 < d.N) ? src[3] : 0.f;
                }
            }
            // ---- compute on buf: conflict-free LDS.64 + FMA2 inner loop ----
            #pragma unroll
            for (int kk = 0; kk < 16; kk++) {
                const u64 a0 = *(const u64*)&sA[buf][kk][ty*8 + 0];
                const u64 a1 = *(const u64*)&sA[buf][kk][ty*8 + 2];
                const u64 a2 = *(const u64*)&sA[buf][kk][ty*8 + 4];
                const u64 a3 = *(const u64*)&sA[buf][kk][ty*8 + 6];
                const u64 b0 = *(const u64*)&sBw[buf][kk][wb + 0];
                const u64 b1 = *(const u64*)&sBw[buf][kk][wb + 34];
                const u64 b2 = *(const u64*)&sBw[buf][kk][wb + 68];
                const u64 b3 = *(const u64*)&sBw[buf][kk][wb + 102];
                acc[0][0] = fma2_(a0, b0, acc[0][0]);
                acc[1][0] = fma2_(a1, b0, acc[1][0]);
                acc[2][0] = fma2_(a2, b0, acc[2][0]);
                acc[3][0] = fma2_(a3, b0, acc[3][0]);
                acc[0][1] = fma2_(a0, b1, acc[0][1]);
                acc[1][1] = fma2_(a1, b1, acc[1][1]);
                acc[2][1] = fma2_(a2, b1, acc[2][1]);
                acc[3][1] = fma2_(a3, b1, acc[3][1]);
                acc[0][2] = fma2_(a0, b2, acc[0][2]);
                acc[1][2] = fma2_(a1, b2, acc[1][2]);
                acc[2][2] = fma2_(a2, b2, acc[2][2]);
                acc[3][2] = fma2_(a3, b2, acc[3][2]);
                acc[0][3] = fma2_(a0, b3, acc[0][3]);
                acc[1][3] = fma2_(a1, b3, acc[1][3]);
                acc[2][3] = fma2_(a2, b3, acc[2][3]);
                acc[3][3] = fma2_(a3, b3, acc[3][3]);
            }
            if (more) {
                const int nbuf = buf ^ 1;
                sA[nbuf][ca+0][ra] = na0.x; sA[nbuf][ca+1][ra] = na0.y;
                sA[nbuf][ca+2][ra] = na0.z; sA[nbuf][ca+3][ra] = na0.w;
                sA[nbuf][ca+4][ra] = na1.x; sA[nbuf][ca+5][ra] = na1.y;
                sA[nbuf][ca+6][ra] = na1.z; sA[nbuf][ca+7][ra] = na1.w;
                if (d.transB) {
                    *(float2*)&sBw[nbuf][cb+0][wo_nt] = make_float2(nb.x, nb.x);
                    *(float2*)&sBw[nbuf][cb+1][wo_nt] = make_float2(nb.y, nb.y);
                    *(float2*)&sBw[nbuf][cb+2][wo_nt] = make_float2(nb.z, nb.z);
                    *(float2*)&sBw[nbuf][cb+3][wo_nt] = make_float2(nb.w, nb.w);
                } else {
                    *(float2*)&sBw[nbuf][nkk][bwoff_(nn4+0)] = make_float2(nb.x, nb.x);
                    *(float2*)&sBw[nbuf][nkk][bwoff_(nn4+1)] = make_float2(nb.y, nb.y);
                    *(float2*)&sBw[nbuf][nkk][bwoff_(nn4+2)] = make_float2(nb.z, nb.z);
                    *(float2*)&sBw[nbuf][nkk][bwoff_(nn4+3)] = make_float2(nb.w, nb.w);
                }
            }
            __syncthreads();
            buf ^= 1;
        }
    }

    // ---- epilogue ----
    const int n0 = bn + tx*4;
    const int m0 = bm + ty*8;
    float bb[4] = {0.f, 0.f, 0.f, 0.f};
    if (d.bias) {
        #pragma unroll
        for (int j = 0; j < 4; j++) if (n0 + j < d.N) bb[j] = d.bias[n0 + j];
    }
    const bool vec = ((d.ldc & 3) == 0) && ((((size_t)C) & 15) == 0) && (bn + 64 <= d.N);
    #pragma unroll
    for (int p = 0; p < 4; p++) {
        const float2 v0 = unpk_(acc[p][0]);
        const float2 v1 = unpk_(acc[p][1]);
        const float2 v2 = unpk_(acc[p][2]);
        const float2 v3 = unpk_(acc[p][3]);
        float4 r0 = make_float4(v0.x + bb[0], v1.x + bb[1], v2.x + bb[2], v3.x + bb[3]);
        float4 r1 = make_float4(v0.y + bb[0], v1.y + bb[1], v2.y + bb[2], v3.y + bb[3]);
        if (d.act) {
            r0.x = tanhf(r0.x); r0.y = tanhf(r0.y); r0.z = tanhf(r0.z); r0.w = tanhf(r0.w);
            r1.x = tanhf(r1.x); r1.y = tanhf(r1.y); r1.z = tanhf(r1.z); r1.w = tanhf(r1.w);
        }
        const int m = m0 + 2*p;
        if (vec) {
            *(float4*)(C + (size_t)m*d.ldc + n0)     = r0;
            *(float4*)(C + (size_t)(m+1)*d.ldc + n0) = r1;
        } else {
            const float rr0[4] = {r0.x, r0.y, r0.z, r0.w};
            const float rr1[4] = {r1.x, r1.y, r1.z, r1.w};
            #pragma unroll
            for (int j = 0; j < 4; j++) {
                if (n0 + j < d.N) {
                    C[(size_t)m*d.ldc + n0 + j]     = rr0[j];
                    C[(size_t)(m+1)*d.ldc + n0 + j] = rr1[j];
                }
            }
        }
    }
}

// ---------------- per-step bilinear matvecs (fp32, 4 rows/warp, float4) ------
__global__ void bilinear_kernel(int t, const float* __restrict__ bg_b,
                                const float* __restrict__ bw_b,
                                const float* __restrict__ out)
{
    const int b = blockIdx.x;
    __shared__ __align__(16) float zs[JZP];
    const int tid = threadIdx.x;
    for (int i = tid; i < JZP; i += blockDim.x) {
        float v = 0.f;
        if (i < DOF)            v = out[(size_t)b*MS*DOF + t*DOF + i];
        else if (i - DOF < WSZ) v = out[GOFF + (size_t)b*MS*WSZ + t*WSZ + (i - DOF)];
        zs[i] = v;
    }
    __syncthreads();
    if (blockIdx.y < PW/32) {
        const int w = tid >> 5;
        const int lane = tid & 31;
        const int o0 = blockIdx.y * 32 + w * 4;
        const float4* m0 = (const float4*)(d_Mw + ((size_t)b*PW + o0 + 0)*JZP);
        const float4* m1 = (const float4*)(d_Mw + ((size_t)b*PW + o0 + 1)*JZP);
        const float4* m2 = (const float4*)(d_Mw + ((size_t)b*PW + o0 + 2)*JZP);
        const float4* m3 = (const float4*)(d_Mw + ((size_t)b*PW + o0 + 3)*JZP);
        const float4* z4 = (const float4*)zs;
        float s0 = 0.f, s1 = 0.f, s2 = 0.f, s3 = 0.f;
        #pragma unroll 1
        for (int j4 = lane; j4 < JZP/4; j4 += 32) {
            const float4 zv = z4[j4];
            const float4 v0 = m0[j4];
            const float4 v1 = m1[j4];
            const float4 v2 = m2[j4];
            const float4 v3 = m3[j4];
            s0 += v0.x*zv.x + v0.y*zv.y + v0.z*zv.z + v0.w*zv.w;
            s1 += v1.x*zv.x + v1.y*zv.y + v1.z*zv.z + v1.w*zv.w;
            s2 += v2.x*zv.x + v2.y*zv.y + v2.z*zv.z + v2.w*zv.w;
            s3 += v3.x*zv.x + v3.y*zv.y + v3.z*zv.z + v3.w*zv.w;
        }
        #pragma unroll
        for (int off = 16; off; off >>= 1) {
            s0 += __shfl_down_sync(0xffffffffu, s0, off);
            s1 += __shfl_down_sync(0xffffffffu, s1, off);
            s2 += __shfl_down_sync(0xffffffffu, s2, off);
            s3 += __shfl_down_sync(0xffffffffu, s3, off);
        }
        if (lane == 0) {
            d_ypre[b*PW + o0 + 0] = s0 + bw_b[o0 + 0];
            d_ypre[b*PW + o0 + 1] = s1 + bw_b[o0 + 1];
            d_ypre[b*PW + o0 + 2] = s2 + bw_b[o0 + 2];
            d_ypre[b*PW + o0 + 3] = s3 + bw_b[o0 + 3];
        }
    } else {
        // x branch: tid is o (256 outputs, 6-elem dot), fp32 Mg
        const float* mg = d_Mg + ((size_t)b*PG + tid)*DOF;
        float s = bg_b[tid];
        #pragma unroll
        for (int j = 0; j < DOF; j++) s += mg[j] * zs[j];
        d_xpre[b*PG + tid] = s;
    }
}

// ---------------- merged LSTM pointwise (g-chain + w-chain) ------------------
__global__ void lstm_point2_kernel(const float* __restrict__ gg, const float* __restrict__ gw,
                                   float* __restrict__ hgp, float* __restrict__ cgp,
                                   float* __restrict__ hwp, float* __restrict__ cwp)
{
    int idx = blockIdx.x * blockDim.x + threadIdx.x;
    const float* gates; float* h; float* c; int H;
    if (idx < BB*HG) { gates = gg; h = hgp; c = cgp; H = HG; }
    else {
        idx -= BB*HG;
        if (idx >= BB*HW) return;
        gates = gw; h = hwp; c = cwp; H = HW;
    }
    const int b = idx / H, j = idx % H;
    const float* g = gates + (size_t)b*4*H;
    const float ig = sigmoidf_(g[j]);
    const float fg = sigmoidf_(g[H + j]);
    const float gv = tanhf(g[2*H + j]);
    const float og = sigmoidf_(g[3*H + j]);
    const float cn = fg * c[idx] + ig * gv;
    c[idx] = cn;
    h[idx] = og * tanhf(cn);
}

// ---------------- host helpers -----------------------------------------------
static inline GDesc mk(const float* A, int lda, const float* B, int ldb, int transB,
                       const float* A2, int lda2, const float* B2, int ldb2,
                       const float* bias, float* C, int ldc,
                       int M, int N, int K, int K2, int act,
                       long long sB = 0, long long sC = 0)
{
    GDesc d;
    d.A = A; d.B = B; d.A2 = A2; d.B2 = B2; d.bias = bias; d.C = C;
    d.lda = lda; d.ldb = ldb; d.lda2 = lda2; d.ldb2 = ldb2; d.ldc = ldc;
    d.M = M; d.N = N; d.K = K; d.K2 = K2;
    d.transB = transB; d.act = act; d.gx = (N + 63) / 64;
    d.strideB = sB; d.strideC = sC;
    return d;
}

extern "C" void kernel_launch(void* const* d_in, const int* in_sizes, int n_in,
                              void* d_out, int out_size)
{
    const float* ctx    = (const float*)d_in[0];
    const float* goal0  = (const float*)d_in[1];
    const float* w0     = (const float*)d_in[2];
    const float* bg_W   = (const float*)d_in[3];
    const float* bg_b   = (const float*)d_in[4];
    const float* bw_W   = (const float*)d_in[5];
    const float* bw_b   = (const float*)d_in[6];
    const float* fcg_W  = (const float*)d_in[7];
    const float* fcg_b  = (const float*)d_in[8];
    const float* fcw_W  = (const float*)d_in[9];
    const float* fcw_b  = (const float*)d_in[10];
    const float* lg_Wih = (const float*)d_in[11];
    const float* lg_Whh = (const float*)d_in[12];
    const float* lg_bih = (const float*)d_in[13];
    const float* lg_bhh = (const float*)d_in[14];
    const float* lw_Wih = (const float*)d_in[15];
    const float* lw_Whh = (const float*)d_in[16];
    const float* lw_bih = (const float*)d_in[17];
    const float* lw_bhh = (const float*)d_in[18];
    const float* og_W   = (const float*)d_in[19];
    const float* og_b   = (const float*)d_in[20];
    const float* ow_W   = (const float*)d_in[21];
    const float* ow_b   = (const float*)d_in[22];
    float* out = (float*)d_out;

    float *Mw, *xpre, *ypre, *xg, *yw, *gh, *gc, *wh, *wc, *ggb, *gwb, *bias_g, *bias_w;
    cudaGetSymbolAddress((void**)&Mw, d_Mw);
    cudaGetSymbolAddress((void**)&xpre, d_xpre);
    cudaGetSymbolAddress((void**)&ypre, d_ypre);
    cudaGetSymbolAddress((void**)&xg, d_xg);
    cudaGetSymbolAddress((void**)&yw, d_yw);
    cudaGetSymbolAddress((void**)&gh, d_gh);
    cudaGetSymbolAddress((void**)&gc, d_gc);
    cudaGetSymbolAddress((void**)&wh, d_wh);
    cudaGetSymbolAddress((void**)&wc, d_wc);
    cudaGetSymbolAddress((void**)&ggb, d_gates_g);
    cudaGetSymbolAddress((void**)&gwb, d_gates_w);
    cudaGetSymbolAddress((void**)&bias_g, d_bias_g);
    cudaGetSymbolAddress((void**)&bias_w, d_bias_w);

    GDesc empty = {};
    empty.M = 0; empty.gx = 0;

    // --- init + precompute (context is step-invariant) ---
    init_kernel<<<256, 256>>>(goal0, w0, lg_bih, lg_bhh, lw_bih, lw_bhh, out);
    pre_Mg_kernel<<<PG, 256>>>(ctx, bg_W);

    // M_w[b,o,j] = sum_i ctx[b,i] * bw_W[o,i,j] : batched over o (z = o)
    {
        GDesc dmw = mk(ctx, CTXD, bw_W, JZ, /*transB=*/0,
                       nullptr, 0, nullptr, 0, nullptr,
                       Mw, PW*JZP, BB, JZ, CTXD, 0, 0,
                       (long long)CTXD*JZ, (long long)JZP);
        gemm2_kernel<<<dim3(dmw.gx, BB/128, PW), 256>>>(dmw, empty, PW);
    }

    for (int t = 0; t < STEPS; ++t) {
        // 1. bilinear matvecs
        bilinear_kernel<<<dim3(BB, PW/32 + 1), 256>>>(t, bg_b, bw_b, out);

        // 2. fc + tanh (both branches, one launch)
        {
            GDesc dg = mk(xpre, PG, fcg_W, PG, 1, nullptr, 0, nullptr, 0,
                          fcg_b, xg, PG, BB, PG, PG, 0, 1);
            GDesc dw = mk(ypre, PW, fcw_W, PW, 1, nullptr, 0, nullptr, 0,
                          fcw_b, yw, PW, BB, PW, PW, 0, 1);
            int gx = dg.gx > dw.gx ? dg.gx : dw.gx;
            gemm2_kernel<<<dim3(gx, BB/128, 2), 256>>>(dg, dw, 1);
        }

        // 3+4. LSTM layers (g-chain and w-chain gate GEMMs merged per layer)
        for (int l = 0; l < NL; ++l) {
            const float* ing = (l == 0) ? xg : gh;
            const float* inw = (l == 0) ? yw : wh;
            GDesc dg = mk(ing, (l == 0) ? PG : HG,
                          lg_Wih + (size_t)l*4*HG*PG, (l == 0) ? PG : HG, 1,
                          gh + (size_t)l*BB*HG, HG,
                          lg_Whh + (size_t)l*4*HG*HG, HG,
                          bias_g + l*4*HG, ggb, 4*HG,
                          BB, 4*HG, (l == 0) ? PG : HG, HG, 0);
            GDesc dw = mk(inw, (l == 0) ? PW : HW,
                          lw_Wih + (size_t)l*4*HW*PW, (l == 0) ? PW : HW, 1,
                          wh + (size_t)l*BB*HW, HW,
                          lw_Whh + (size_t)l*4*HW*HW, HW,
                          bias_w + l*4*HW, gwb, 4*HW,
                          BB, 4*HW, (l == 0) ? PW : HW, HW, 0);
            int gx = dg.gx > dw.gx ? dg.gx : dw.gx;
            gemm2_kernel<<<dim3(gx, BB/128, 2), 256>>>(dg, dw, 1);
            lstm_point2_kernel<<<(BB*HG + BB*HW + 255)/256, 256>>>(
                ggb, gwb,
                gh + (size_t)l*BB*HG, gc + (size_t)l*BB*HG,
                wh + (size_t)l*BB*HW, wc + (size_t)l*BB*HW);
        }

        // 5. output projections (merged), written into out rows t+1
        {
            GDesc dg = mk(gh + (size_t)1*BB*HG, HG, og_W, HG, 1, nullptr, 0, nullptr, 0,
                          og_b, out + (t + 1)*DOF, MS*DOF, BB, DOF, HG, 0, 0);
            GDesc dw = mk(wh + (size_t)1*BB*HW, HW, ow_W, HW, 1, nullptr, 0, nullptr, 0,
                          ow_b, out + GOFF + (t + 1)*WSZ, MS*WSZ, BB, WSZ, HW, 0, 0);
            int gx = dg.gx > dw.gx ? dg.gx : dw.gx;
            gemm2_kernel<<<dim3(gx, BB/128, 2), 256>>>(dg, dw, 1);
        }
    }
}